// round 12
// baseline (speedup 1.0000x reference)
#include <cuda_runtime.h>
#include <cstdint>

#define N_NODES 50000
#define N_EDGES 800000
#define IN_DIM  256
#define HIDDEN  128
#define OUT_DIM 64
#define NEG_SLOPE 0.1f

#define SCAN_B 256
#define NSCAN_BLOCKS ((N_NODES + SCAN_B - 1) / SCAN_B)   // 196

// ---------------- scratch (no allocations allowed) ----------------
__device__ __align__(16) float g_dinv[N_NODES];
__device__ __align__(16) float g_h   [N_NODES * HIDDEN];
__device__ __align__(16) float g_t   [N_NODES * HIDDEN];
__device__ int  g_cnt   [N_NODES];
__device__ int  g_cursor[N_NODES];
__device__ int  g_rowptr[N_NODES + 1];
__device__ int  g_bsum  [SCAN_B];
__device__ __align__(8) int2 g_edge [N_EDGES];   // {src, bitcast(dinv[src])}
__device__ int  g_is32;

// ---------------- packed f32x2 helpers ----------------
__device__ __forceinline__ unsigned long long pack_dup(float a) {
    unsigned long long r;
    asm("mov.b64 %0, {%1, %1};" : "=l"(r) : "r"(__float_as_int(a)));
    return r;
}
__device__ __forceinline__ void fma_f32x2(unsigned long long& acc,
                                          unsigned long long a, unsigned long long b) {
    asm("fma.rn.f32x2 %0, %1, %2, %0;" : "+l"(acc) : "l"(a), "l"(b));
}
__device__ __forceinline__ void unpack_f32x2(unsigned long long v, float& lo, float& hi) {
    int a, b;
    asm("mov.b64 {%0, %1}, %2;" : "=r"(a), "=r"(b) : "l"(v));
    lo = __int_as_float(a); hi = __int_as_float(b);
}

// ---------------- edge index access (int32 or int64) ----------------
__device__ __forceinline__ int edge_at(const void* ei, int i, int is32, int half) {
    if (is32) return ((const int*)ei)[half * N_EDGES + i];
    return (int)((const long long*)ei)[half * N_EDGES + i];
}

__global__ void k_detect(const void* __restrict__ ei, int* __restrict__ flag) {
    if (threadIdx.x == 0 && blockIdx.x == 0) {
        const long long* p = (const long long*)ei;
        int is32 = 0;
        for (int i = 0; i < 64; i++) {
            long long v = p[i];
            if (v < 0 || v >= N_NODES) { is32 = 1; break; }
        }
        *flag = is32;
    }
}

// ---------------- CSR build ----------------
__global__ void k_hist_init(int* __restrict__ cnt, int* __restrict__ cur, int n) {
    int i = blockIdx.x * blockDim.x + threadIdx.x;
    if (i < n) { cnt[i] = 0; cur[i] = 0; }
}

__global__ void k_hist(const void* __restrict__ ei, int* __restrict__ cnt,
                       const int* __restrict__ flag, int e) {
    int i = blockIdx.x * blockDim.x + threadIdx.x;
    if (i >= e) return;
    int d = edge_at(ei, i, *flag, 1);
    if ((unsigned)d < N_NODES) atomicAdd(&cnt[d], 1);
}

__global__ void k_dinv(const int* __restrict__ cnt, float* __restrict__ dinv, int n) {
    int i = blockIdx.x * blockDim.x + threadIdx.x;
    if (i < n) dinv[i] = rsqrtf((float)(cnt[i] + 1));   // +1 self loop
}

// exclusive scan, 3 phases
__global__ void k_scan1(const int* __restrict__ cnt, int* __restrict__ rowptr,
                        int* __restrict__ bsum, int n) {
    __shared__ int s[SCAN_B];
    int i = blockIdx.x * SCAN_B + threadIdx.x;
    int v = (i < n) ? cnt[i] : 0;
    s[threadIdx.x] = v;
    __syncthreads();
    int acc = v;
#pragma unroll
    for (int off = 1; off < SCAN_B; off <<= 1) {
        int add = (threadIdx.x >= off) ? s[threadIdx.x - off] : 0;
        __syncthreads();
        acc += add;
        s[threadIdx.x] = acc;
        __syncthreads();
    }
    if (i < n) rowptr[i] = acc - v;              // local exclusive
    if (threadIdx.x == SCAN_B - 1) bsum[blockIdx.x] = acc;
}

__global__ void k_scan2(int* __restrict__ bsum, int nb) {
    __shared__ int s[SCAN_B];
    int v = (threadIdx.x < nb) ? bsum[threadIdx.x] : 0;
    s[threadIdx.x] = v;
    __syncthreads();
    int acc = v;
#pragma unroll
    for (int off = 1; off < SCAN_B; off <<= 1) {
        int add = (threadIdx.x >= off) ? s[threadIdx.x - off] : 0;
        __syncthreads();
        acc += add;
        s[threadIdx.x] = acc;
        __syncthreads();
    }
    if (threadIdx.x < nb) bsum[threadIdx.x] = acc - v;   // exclusive
}

__global__ void k_scan3(int* __restrict__ rowptr, const int* __restrict__ bsum, int n) {
    int i = blockIdx.x * SCAN_B + threadIdx.x;
    if (i < n) rowptr[i] += bsum[blockIdx.x];
    if (i == 0) rowptr[n] = N_EDGES;
}

__global__ void k_fill(const void* __restrict__ ei, const int* __restrict__ rowptr,
                       int* __restrict__ cur, const float* __restrict__ dinv,
                       int2* __restrict__ edge, const int* __restrict__ flag, int e) {
    int i = blockIdx.x * blockDim.x + threadIdx.x;
    if (i >= e) return;
    int is32 = *flag;
    int s = edge_at(ei, i, is32, 0);
    int d = edge_at(ei, i, is32, 1);
    if ((unsigned)s >= N_NODES || (unsigned)d >= N_NODES) return;
    int pos = rowptr[d] + atomicAdd(&cur[d], 1);
    edge[pos] = make_int2(s, __float_as_int(dinv[s]));
}

// ---------------- fused aggregation: one warp per dst node ----------------
__global__ void __launch_bounds__(256) k_gather(
    const int* __restrict__ rowptr, const int2* __restrict__ edge,
    const float* __restrict__ dinv, const float* __restrict__ t,
    const float* __restrict__ bias, float* __restrict__ h, int n)
{
    int d = blockIdx.x * 8 + (threadIdx.x >> 5);
    if (d >= n) return;
    int lane = threadIdx.x & 31;
    float dd = dinv[d];

    float4 acc = ((const float4*)(t + (size_t)d * HIDDEN))[lane];
    float w0 = dd * dd;
    acc.x *= w0; acc.y *= w0; acc.z *= w0; acc.w *= w0;

    int j   = rowptr[d];
    int end = rowptr[d + 1];
    for (; j + 3 < end; j += 4) {
        int2 e0 = edge[j];
        int2 e1 = edge[j + 1];
        int2 e2 = edge[j + 2];
        int2 e3 = edge[j + 3];
        float4 v0 = ((const float4*)(t + (size_t)e0.x * HIDDEN))[lane];
        float4 v1 = ((const float4*)(t + (size_t)e1.x * HIDDEN))[lane];
        float4 v2 = ((const float4*)(t + (size_t)e2.x * HIDDEN))[lane];
        float4 v3 = ((const float4*)(t + (size_t)e3.x * HIDDEN))[lane];
        float wa = __int_as_float(e0.y) * dd;
        float wb = __int_as_float(e1.y) * dd;
        float wc = __int_as_float(e2.y) * dd;
        float wd = __int_as_float(e3.y) * dd;
        acc.x = fmaf(v0.x, wa, acc.x); acc.y = fmaf(v0.y, wa, acc.y);
        acc.z = fmaf(v0.z, wa, acc.z); acc.w = fmaf(v0.w, wa, acc.w);
        acc.x = fmaf(v1.x, wb, acc.x); acc.y = fmaf(v1.y, wb, acc.y);
        acc.z = fmaf(v1.z, wb, acc.z); acc.w = fmaf(v1.w, wb, acc.w);
        acc.x = fmaf(v2.x, wc, acc.x); acc.y = fmaf(v2.y, wc, acc.y);
        acc.z = fmaf(v2.z, wc, acc.z); acc.w = fmaf(v2.w, wc, acc.w);
        acc.x = fmaf(v3.x, wd, acc.x); acc.y = fmaf(v3.y, wd, acc.y);
        acc.z = fmaf(v3.z, wd, acc.z); acc.w = fmaf(v3.w, wd, acc.w);
    }
    for (; j < end; j++) {
        int2 e0 = edge[j];
        float wa = __int_as_float(e0.y) * dd;
        float4 v0 = ((const float4*)(t + (size_t)e0.x * HIDDEN))[lane];
        acc.x = fmaf(v0.x, wa, acc.x); acc.y = fmaf(v0.y, wa, acc.y);
        acc.z = fmaf(v0.z, wa, acc.z); acc.w = fmaf(v0.w, wa, acc.w);
    }

    float4 b = *(const float4*)(bias + lane * 4);
    acc.x += b.x; acc.y += b.y; acc.z += b.z; acc.w += b.w;
    acc.x = acc.x > 0.f ? acc.x : acc.x * NEG_SLOPE;
    acc.y = acc.y > 0.f ? acc.y : acc.y * NEG_SLOPE;
    acc.z = acc.z > 0.f ? acc.z : acc.z * NEG_SLOPE;
    acc.w = acc.w > 0.f ? acc.w : acc.w * NEG_SLOPE;
    ((float4*)(h + (size_t)d * HIDDEN))[lane] = acc;
}

// ---------------- SGEMM 128x128x16, 8x8/thread, f32x2 FMA, double-buffered ----------------
__global__ void __launch_bounds__(256) sgemm128(
    const float* __restrict__ A, const float* __restrict__ B,
    const float* __restrict__ bias, float* __restrict__ C,
    int M, int N, int K, int act)
{
    const int BM = 128, BN = 128, BK = 16;
    __shared__ float As[2][BK][BM];
    __shared__ float Bs[2][BK][BN];

    int t = threadIdx.x;
    int bm0 = blockIdx.y * BM;
    int bn0 = blockIdx.x * BN;

    int trow = t >> 4;
    int tcol = t & 15;

    // loader geometry (2 float4 per thread for each of A, B)
    int a_row0 = t >> 2;                 // 0..63   (u=0)
    int a_row1 = a_row0 + 64;            // 64..127 (u=1)
    int a_k4   = (t & 3) * 4;
    int b_r0   = t >> 5;                 // 0..7    (u=0)
    int b_r1   = b_r0 + 8;               // 8..15   (u=1)
    int b_c4   = (t & 31) * 4;

    unsigned long long accp[8][4];
#pragma unroll
    for (int i = 0; i < 8; i++)
#pragma unroll
        for (int j = 0; j < 4; j++) accp[i][j] = 0ULL;

    int nk = K / BK;

    // prologue: load tile 0 into buffer 0
    {
        float4 va0 = make_float4(0.f,0.f,0.f,0.f), va1 = va0;
        int gr0 = bm0 + a_row0, gr1 = bm0 + a_row1;
        if (gr0 < M) va0 = *(const float4*)(A + (size_t)gr0 * K + a_k4);
        if (gr1 < M) va1 = *(const float4*)(A + (size_t)gr1 * K + a_k4);
        float4 vb0 = *(const float4*)(B + (size_t)b_r0 * N + bn0 + b_c4);
        float4 vb1 = *(const float4*)(B + (size_t)b_r1 * N + bn0 + b_c4);
        As[0][a_k4 + 0][a_row0] = va0.x; As[0][a_k4 + 1][a_row0] = va0.y;
        As[0][a_k4 + 2][a_row0] = va0.z; As[0][a_k4 + 3][a_row0] = va0.w;
        As[0][a_k4 + 0][a_row1] = va1.x; As[0][a_k4 + 1][a_row1] = va1.y;
        As[0][a_k4 + 2][a_row1] = va1.z; As[0][a_k4 + 3][a_row1] = va1.w;
        *(float4*)&Bs[0][b_r0][b_c4] = vb0;
        *(float4*)&Bs[0][b_r1][b_c4] = vb1;
    }
    __syncthreads();

    for (int kt = 0; kt < nk; kt++) {
        int cur = kt & 1;
        // prefetch next tile into registers (overlaps with compute below)
        float4 va0, va1, vb0, vb1;
        bool have_next = (kt + 1 < nk);
        if (have_next) {
            int k0 = (kt + 1) * BK;
            va0 = make_float4(0.f,0.f,0.f,0.f); va1 = va0;
            int gr0 = bm0 + a_row0, gr1 = bm0 + a_row1;
            if (gr0 < M) va0 = *(const float4*)(A + (size_t)gr0 * K + k0 + a_k4);
            if (gr1 < M) va1 = *(const float4*)(A + (size_t)gr1 * K + k0 + a_k4);
            vb0 = *(const float4*)(B + (size_t)(k0 + b_r0) * N + bn0 + b_c4);
            vb1 = *(const float4*)(B + (size_t)(k0 + b_r1) * N + bn0 + b_c4);
        }

#pragma unroll
        for (int kk = 0; kk < BK; kk++) {
            float ar[8];
            *(float4*)&ar[0] = *(const float4*)&As[cur][kk][trow * 8];
            *(float4*)&ar[4] = *(const float4*)&As[cur][kk][trow * 8 + 4];
            ulonglong2 q0 = *(const ulonglong2*)&Bs[cur][kk][tcol * 8];
            ulonglong2 q1 = *(const ulonglong2*)&Bs[cur][kk][tcol * 8 + 4];
            unsigned long long bb[4] = {q0.x, q0.y, q1.x, q1.y};
#pragma unroll
            for (int i = 0; i < 8; i++) {
                unsigned long long aa = pack_dup(ar[i]);
#pragma unroll
                for (int j = 0; j < 4; j++)
                    fma_f32x2(accp[i][j], aa, bb[j]);
            }
        }

        if (have_next) {
            int nxt = cur ^ 1;
            As[nxt][a_k4 + 0][a_row0] = va0.x; As[nxt][a_k4 + 1][a_row0] = va0.y;
            As[nxt][a_k4 + 2][a_row0] = va0.z; As[nxt][a_k4 + 3][a_row0] = va0.w;
            As[nxt][a_k4 + 0][a_row1] = va1.x; As[nxt][a_k4 + 1][a_row1] = va1.y;
            As[nxt][a_k4 + 2][a_row1] = va1.z; As[nxt][a_k4 + 3][a_row1] = va1.w;
            *(float4*)&Bs[nxt][b_r0][b_c4] = vb0;
            *(float4*)&Bs[nxt][b_r1][b_c4] = vb1;
            __syncthreads();
        }
    }

    float bv[8] = {0,0,0,0,0,0,0,0};
    if (bias) {
        *(float4*)&bv[0] = *(const float4*)(bias + bn0 + tcol * 8);
        *(float4*)&bv[4] = *(const float4*)(bias + bn0 + tcol * 8 + 4);
    }
#pragma unroll
    for (int i = 0; i < 8; i++) {
        int gr = bm0 + trow * 8 + i;
        if (gr >= M) continue;
        float o[8];
#pragma unroll
        for (int j = 0; j < 4; j++)
            unpack_f32x2(accp[i][j], o[2 * j], o[2 * j + 1]);
#pragma unroll
        for (int j = 0; j < 8; j++) {
            float v = o[j] + bv[j];
            if (act) v = v > 0.f ? v : v * NEG_SLOPE;
            o[j] = v;
        }
        *(float4*)(C + (size_t)gr * N + bn0 + tcol * 8)     = *(float4*)&o[0];
        *(float4*)(C + (size_t)gr * N + bn0 + tcol * 8 + 4) = *(float4*)&o[4];
    }
}

// ---------------- SGEMM 64x64x16 (dec, N=64), packed f32x2 FMA ----------------
__global__ void __launch_bounds__(256) sgemm64(
    const float* __restrict__ A, const float* __restrict__ B,
    const float* __restrict__ bias, float* __restrict__ C,
    int M, int N, int K, int act)
{
    const int BM = 64, BN = 64, BK = 16;
    __shared__ float As[BK][BM];
    __shared__ float Bs[BK][BN];

    int t = threadIdx.x;
    int bm0 = blockIdx.y * BM;
    int bn0 = blockIdx.x * BN;

    int a_row = t >> 2;
    int a_k4  = (t & 3) * 4;
    int b_row = t >> 4;
    int b_c4  = (t & 15) * 4;
    int trow = t >> 4;
    int tcol = t & 15;

    unsigned long long accp[4][2];
#pragma unroll
    for (int i = 0; i < 4; i++) { accp[i][0] = 0ULL; accp[i][1] = 0ULL; }

    for (int k0 = 0; k0 < K; k0 += BK) {
        {
            int gr = bm0 + a_row;
            float4 v = make_float4(0.f, 0.f, 0.f, 0.f);
            if (gr < M) v = *(const float4*)(A + (size_t)gr * K + k0 + a_k4);
            As[a_k4 + 0][a_row] = v.x;
            As[a_k4 + 1][a_row] = v.y;
            As[a_k4 + 2][a_row] = v.z;
            As[a_k4 + 3][a_row] = v.w;
        }
        {
            float4 v = *(const float4*)(B + (size_t)(k0 + b_row) * N + bn0 + b_c4);
            *(float4*)&Bs[b_row][b_c4] = v;
        }
        __syncthreads();

#pragma unroll
        for (int kk = 0; kk < BK; kk++) {
            float4 a = *(const float4*)&As[kk][trow * 4];
            ulonglong2 q = *(const ulonglong2*)&Bs[kk][tcol * 4];
            unsigned long long bb[2] = {q.x, q.y};
            float ar[4] = {a.x, a.y, a.z, a.w};
#pragma unroll
            for (int i = 0; i < 4; i++) {
                unsigned long long aa = pack_dup(ar[i]);
                fma_f32x2(accp[i][0], aa, bb[0]);
                fma_f32x2(accp[i][1], aa, bb[1]);
            }
        }
        __syncthreads();
    }

    float4 bv = make_float4(0.f, 0.f, 0.f, 0.f);
    if (bias) bv = *(const float4*)(bias + bn0 + tcol * 4);
#pragma unroll
    for (int i = 0; i < 4; i++) {
        int gr = bm0 + trow * 4 + i;
        if (gr >= M) continue;
        float4 o;
        unpack_f32x2(accp[i][0], o.x, o.y);
        unpack_f32x2(accp[i][1], o.z, o.w);
        o.x += bv.x; o.y += bv.y; o.z += bv.z; o.w += bv.w;
        if (act) {
            o.x = o.x > 0.f ? o.x : o.x * NEG_SLOPE;
            o.y = o.y > 0.f ? o.y : o.y * NEG_SLOPE;
            o.z = o.z > 0.f ? o.z : o.z * NEG_SLOPE;
            o.w = o.w > 0.f ? o.w : o.w * NEG_SLOPE;
        }
        *(float4*)(C + (size_t)gr * N + bn0 + tcol * 4) = o;
    }
}

// ---------------- launch ----------------
extern "C" void kernel_launch(void* const* d_in, const int* in_sizes, int n_in,
                              void* d_out, int out_size)
{
    const float *x = 0, *enc_W = 0, *enc_b = 0, *conv_W = 0, *conv_b = 0, *dec_W = 0, *dec_b = 0;
    const void  *ei = 0;
    for (int i = 0; i < n_in; i++) {
        int sz = in_sizes[i];
        const void* p = d_in[i];
        switch (sz) {
            case 12800000: x      = (const float*)p; break;
            case 1600000:  ei     = p;               break;
            case 128:      enc_b  = (const float*)p; break;
            case 256:      conv_b = (const float*)p; break;
            case 8192:     dec_W  = (const float*)p; break;
            case 64:       dec_b  = (const float*)p; break;
            case 32768: {
                int nxt = (i + 1 < n_in) ? in_sizes[i + 1] : -1;
                if (nxt == 128)      enc_W  = (const float*)p;
                else if (nxt == 256) conv_W = (const float*)p;
                else if (!enc_W)     enc_W  = (const float*)p;
                else                 conv_W = (const float*)p;
                break;
            }
            default: break;
        }
    }
    float* out = (float*)d_out;

    float *dinv, *h, *tbuf;
    int *cnt, *cur, *rowptr, *bsum, *flag;
    int2 *edge;
    cudaGetSymbolAddress((void**)&dinv,   g_dinv);
    cudaGetSymbolAddress((void**)&h,      g_h);
    cudaGetSymbolAddress((void**)&tbuf,   g_t);
    cudaGetSymbolAddress((void**)&cnt,    g_cnt);
    cudaGetSymbolAddress((void**)&cur,    g_cursor);
    cudaGetSymbolAddress((void**)&rowptr, g_rowptr);
    cudaGetSymbolAddress((void**)&bsum,   g_bsum);
    cudaGetSymbolAddress((void**)&edge,   g_edge);
    cudaGetSymbolAddress((void**)&flag,   g_is32);

    const int T = 256;
    int nb_nodes = (N_NODES + T - 1) / T;
    int nb_edges = (N_EDGES + T - 1) / T;

    // Order: encoder GEMM moved to 4th launch (no dependence on CSR chain)
    // so the ncu capture slot lands on the dominant kernel.
    k_detect<<<1, 32>>>(ei, flag);                                     // 1
    k_hist_init<<<nb_nodes, T>>>(cnt, cur, N_NODES);                   // 2
    k_hist<<<nb_edges, T>>>(ei, cnt, flag, N_EDGES);                   // 3
    {
        dim3 grid(HIDDEN / 128, (N_NODES + 127) / 128);                // 4: encoder
        sgemm128<<<grid, 256>>>(x, enc_W, enc_b, h, N_NODES, HIDDEN, IN_DIM, 1);
    }
    k_dinv<<<nb_nodes, T>>>(cnt, dinv, N_NODES);                       // 5
    k_scan1<<<NSCAN_BLOCKS, SCAN_B>>>(cnt, rowptr, bsum, N_NODES);     // 6
    k_scan2<<<1, SCAN_B>>>(bsum, NSCAN_BLOCKS);                        // 7
    k_scan3<<<NSCAN_BLOCKS, SCAN_B>>>(rowptr, bsum, N_NODES);          // 8
    k_fill<<<nb_edges, T>>>(ei, rowptr, cur, dinv, edge, flag, N_EDGES); // 9

    // 2 GCN conv layers: t = h @ W, then fused gather(+bias+lrelu) -> h
    for (int l = 0; l < 2; l++) {
        const float* W = conv_W + (size_t)l * HIDDEN * HIDDEN;
        const float* b = conv_b + (size_t)l * HIDDEN;
        dim3 grid(HIDDEN / 128, (N_NODES + 127) / 128);
        sgemm128<<<grid, 256>>>(h, W, nullptr, tbuf, N_NODES, HIDDEN, HIDDEN, 0);
        k_gather<<<(N_NODES + 7) / 8, 256>>>(rowptr, edge, dinv, tbuf, b, h, N_NODES);
    }

    // decoder: out = h @ dec_W + dec_b
    {
        dim3 grid(OUT_DIM / 64, (N_NODES + 63) / 64);
        sgemm64<<<grid, 256>>>(h, dec_W, dec_b, out, N_NODES, OUT_DIM, HIDDEN, 0);
    }
}

// round 16
// speedup vs baseline: 1.4065x; 1.4065x over previous
#include <cuda_runtime.h>
#include <cuda_bf16.h>
#include <cstdint>

#define N_NODES 50000
#define N_EDGES 800000
#define IN_DIM  256
#define HIDDEN  128
#define OUT_DIM 64
#define NEG_SLOPE 0.1f

#define SCAN_B 256
#define NSCAN_BLOCKS ((N_NODES + SCAN_B - 1) / SCAN_B)   // 196

// ---------------- scratch (no allocations allowed) ----------------
__device__ __align__(16) float g_dinv[N_NODES];
__device__ __align__(16) float g_h   [N_NODES * HIDDEN];
__device__ __align__(16) float g_t   [N_NODES * HIDDEN];
__device__ int  g_cnt   [N_NODES];
__device__ int  g_cursor[N_NODES];
__device__ int  g_rowptr[N_NODES + 1];
__device__ int  g_bsum  [SCAN_B];
__device__ __align__(8) int2 g_edge [N_EDGES];   // {src, bitcast(dinv[src])}
__device__ int  g_is32;

// ---------------- split-bf16 helpers ----------------
// x ≈ hi + lo, both bf16; pack two lanes into one 32-bit reg
__device__ __forceinline__ void cvt2(float x, float y, uint32_t& h, uint32_t& l) {
    __nv_bfloat162 hb = __float22bfloat162_rn(make_float2(x, y));
    float rx = x - __bfloat162float(hb.x);
    float ry = y - __bfloat162float(hb.y);
    __nv_bfloat162 lb = __float22bfloat162_rn(make_float2(rx, ry));
    h = *reinterpret_cast<uint32_t*>(&hb);
    l = *reinterpret_cast<uint32_t*>(&lb);
}

// mma.sync m16n8k16 bf16 (arch-generic; lowers to HMMA on sm_103)
__device__ __forceinline__ void mma16816(float* c, const uint32_t* a,
                                         uint32_t b0, uint32_t b1) {
    asm volatile(
        "mma.sync.aligned.m16n8k16.row.col.f32.bf16.bf16.f32 "
        "{%0,%1,%2,%3}, {%4,%5,%6,%7}, {%8,%9}, {%0,%1,%2,%3};"
        : "+f"(c[0]), "+f"(c[1]), "+f"(c[2]), "+f"(c[3])
        : "r"(a[0]), "r"(a[1]), "r"(a[2]), "r"(a[3]), "r"(b0), "r"(b1));
}

// ---------------- split-bf16 tensor GEMM: C[M,N] = A[M,K] @ W[K,N] ----------------
// CTA tile 128 x N, warps 4(m) x 2(n), warp tile 32 x N/2. K chunks of 32.
// N is compile-time so accumulator indexing fully unrolls.
template<int N>
__global__ void __launch_bounds__(256, 2) mma_gemm(
    const float* __restrict__ A, const float* __restrict__ W,
    const float* __restrict__ bias, float* __restrict__ C,
    int M, int K, int act)
{
    constexpr int PAD = 40;           // bf16 per smem row (80B) -> conflict-free frags
    constexpr int NT  = N / 16;       // 8-col n-tiles per warp
    __shared__ __nv_bfloat16 Ah[128 * PAD], Al[128 * PAD];
    __shared__ __nv_bfloat16 Bh[128 * PAD], Bl[128 * PAD];

    const int tid = threadIdx.x, wid = tid >> 5, lane = tid & 31;
    const int bm0 = blockIdx.x * 128;
    const int wr = wid & 3;           // m slice: rows wr*32 .. +31
    const int wc = wid >> 2;          // n slice: cols wc*N/2 ..
    const int g = lane >> 2, t = lane & 3;

    float acc[2][NT][4];
#pragma unroll
    for (int mt = 0; mt < 2; mt++)
#pragma unroll
        for (int nt = 0; nt < NT; nt++)
#pragma unroll
            for (int q = 0; q < 4; q++) acc[mt][nt][q] = 0.f;

    const int nch = K >> 5;
    for (int kc = 0; kc < nch; kc++) {
        const int k0 = kc << 5;
        __syncthreads();   // previous chunk's frags consumed

        // ---- A loader: rows=nodes, 32 k-cols, fp32 -> hi/lo bf16 ----
        {
            int row  = tid >> 1;
            int col0 = (tid & 1) << 4;
            int gm   = bm0 + row;
            const float* ap = A + (size_t)gm * K + k0 + col0;
#pragma unroll
            for (int j = 0; j < 4; j++) {
                float4 v = (gm < M) ? *(const float4*)(ap + j * 4)
                                    : make_float4(0.f, 0.f, 0.f, 0.f);
                uint32_t h0, l0, h1, l1;
                cvt2(v.x, v.y, h0, l0);
                cvt2(v.z, v.w, h1, l1);
                int c = row * PAD + col0 + j * 4;
                *(uint32_t*)&Ah[c]     = h0;
                *(uint32_t*)&Al[c]     = l0;
                *(uint32_t*)&Ah[c + 2] = h1;
                *(uint32_t*)&Al[c + 2] = l1;
            }
        }
        // ---- B loader: Bs[n][k] = W[k0+k][n] (transpose), hi/lo ----
        {
            int n  = tid >> 1;
            int kb = (tid & 1) << 4;
            if (n < N) {
#pragma unroll
                for (int j = 0; j < 16; j += 2) {
                    float f0 = W[(size_t)(k0 + kb + j)     * N + n];
                    float f1 = W[(size_t)(k0 + kb + j + 1) * N + n];
                    uint32_t hp, lp;
                    cvt2(f0, f1, hp, lp);
                    int c = n * PAD + kb + j;
                    *(uint32_t*)&Bh[c] = hp;
                    *(uint32_t*)&Bl[c] = lp;
                }
            }
        }
        __syncthreads();

        // ---- compute: 2 k16 steps, 3 split passes ----
#pragma unroll
        for (int ks = 0; ks < 2; ks++) {
            const int kb = ks << 4;
            uint32_t ah[2][4], al[2][4];
#pragma unroll
            for (int mt = 0; mt < 2; mt++) {
                int rb = wr * 32 + mt * 16;
                int r0 = (rb + g) * PAD + kb + t * 2;
                int r1 = (rb + 8 + g) * PAD + kb + t * 2;
                ah[mt][0] = *(const uint32_t*)&Ah[r0];
                ah[mt][1] = *(const uint32_t*)&Ah[r1];
                ah[mt][2] = *(const uint32_t*)&Ah[r0 + 8];
                ah[mt][3] = *(const uint32_t*)&Ah[r1 + 8];
                al[mt][0] = *(const uint32_t*)&Al[r0];
                al[mt][1] = *(const uint32_t*)&Al[r1];
                al[mt][2] = *(const uint32_t*)&Al[r0 + 8];
                al[mt][3] = *(const uint32_t*)&Al[r1 + 8];
            }
#pragma unroll
            for (int nt = 0; nt < NT; nt++) {
                int cb = (wc * (N >> 1) + nt * 8 + g) * PAD + kb + t * 2;
                uint32_t bh0 = *(const uint32_t*)&Bh[cb];
                uint32_t bh1 = *(const uint32_t*)&Bh[cb + 8];
                uint32_t bl0 = *(const uint32_t*)&Bl[cb];
                uint32_t bl1 = *(const uint32_t*)&Bl[cb + 8];
#pragma unroll
                for (int mt = 0; mt < 2; mt++) {
                    mma16816(acc[mt][nt], ah[mt], bh0, bh1);  // hi*hi
                    mma16816(acc[mt][nt], al[mt], bh0, bh1);  // lo*hi
                    mma16816(acc[mt][nt], ah[mt], bl0, bl1);  // hi*lo
                }
            }
        }
    }

    // ---- epilogue: bias + lrelu, float2 stores ----
#pragma unroll
    for (int mt = 0; mt < 2; mt++) {
        int row0 = bm0 + wr * 32 + mt * 16 + g;
        int row1 = row0 + 8;
#pragma unroll
        for (int nt = 0; nt < NT; nt++) {
            int col = wc * (N >> 1) + nt * 8 + t * 2;
            float b0 = 0.f, b1 = 0.f;
            if (bias) { b0 = bias[col]; b1 = bias[col + 1]; }
            float c0 = acc[mt][nt][0] + b0, c1 = acc[mt][nt][1] + b1;
            float c2 = acc[mt][nt][2] + b0, c3 = acc[mt][nt][3] + b1;
            if (act) {
                c0 = c0 > 0.f ? c0 : c0 * NEG_SLOPE;
                c1 = c1 > 0.f ? c1 : c1 * NEG_SLOPE;
                c2 = c2 > 0.f ? c2 : c2 * NEG_SLOPE;
                c3 = c3 > 0.f ? c3 : c3 * NEG_SLOPE;
            }
            if (row0 < M) *(float2*)(C + (size_t)row0 * N + col) = make_float2(c0, c1);
            if (row1 < M) *(float2*)(C + (size_t)row1 * N + col) = make_float2(c2, c3);
        }
    }
}

// ---------------- edge index access (int32 or int64) ----------------
__device__ __forceinline__ int edge_at(const void* ei, int i, int is32, int half) {
    if (is32) return ((const int*)ei)[half * N_EDGES + i];
    return (int)((const long long*)ei)[half * N_EDGES + i];
}

__global__ void k_detect(const void* __restrict__ ei, int* __restrict__ flag) {
    if (threadIdx.x == 0 && blockIdx.x == 0) {
        const long long* p = (const long long*)ei;
        int is32 = 0;
        for (int i = 0; i < 64; i++) {
            long long v = p[i];
            if (v < 0 || v >= N_NODES) { is32 = 1; break; }
        }
        *flag = is32;
    }
}

// ---------------- CSR build ----------------
__global__ void k_hist_init(int* __restrict__ cnt, int* __restrict__ cur, int n) {
    int i = blockIdx.x * blockDim.x + threadIdx.x;
    if (i < n) { cnt[i] = 0; cur[i] = 0; }
}

__global__ void k_hist(const void* __restrict__ ei, int* __restrict__ cnt,
                       const int* __restrict__ flag, int e) {
    int i = blockIdx.x * blockDim.x + threadIdx.x;
    if (i >= e) return;
    int d = edge_at(ei, i, *flag, 1);
    if ((unsigned)d < N_NODES) atomicAdd(&cnt[d], 1);
}

__global__ void k_dinv(const int* __restrict__ cnt, float* __restrict__ dinv, int n) {
    int i = blockIdx.x * blockDim.x + threadIdx.x;
    if (i < n) dinv[i] = rsqrtf((float)(cnt[i] + 1));   // +1 self loop
}

__global__ void k_scan1(const int* __restrict__ cnt, int* __restrict__ rowptr,
                        int* __restrict__ bsum, int n) {
    __shared__ int s[SCAN_B];
    int i = blockIdx.x * SCAN_B + threadIdx.x;
    int v = (i < n) ? cnt[i] : 0;
    s[threadIdx.x] = v;
    __syncthreads();
    int acc = v;
#pragma unroll
    for (int off = 1; off < SCAN_B; off <<= 1) {
        int add = (threadIdx.x >= off) ? s[threadIdx.x - off] : 0;
        __syncthreads();
        acc += add;
        s[threadIdx.x] = acc;
        __syncthreads();
    }
    if (i < n) rowptr[i] = acc - v;
    if (threadIdx.x == SCAN_B - 1) bsum[blockIdx.x] = acc;
}

__global__ void k_scan2(int* __restrict__ bsum, int nb) {
    __shared__ int s[SCAN_B];
    int v = (threadIdx.x < nb) ? bsum[threadIdx.x] : 0;
    s[threadIdx.x] = v;
    __syncthreads();
    int acc = v;
#pragma unroll
    for (int off = 1; off < SCAN_B; off <<= 1) {
        int add = (threadIdx.x >= off) ? s[threadIdx.x - off] : 0;
        __syncthreads();
        acc += add;
        s[threadIdx.x] = acc;
        __syncthreads();
    }
    if (threadIdx.x < nb) bsum[threadIdx.x] = acc - v;
}

__global__ void k_scan3(int* __restrict__ rowptr, const int* __restrict__ bsum, int n) {
    int i = blockIdx.x * SCAN_B + threadIdx.x;
    if (i < n) rowptr[i] += bsum[blockIdx.x];
    if (i == 0) rowptr[n] = N_EDGES;
}

__global__ void k_fill(const void* __restrict__ ei, const int* __restrict__ rowptr,
                       int* __restrict__ cur, const float* __restrict__ dinv,
                       int2* __restrict__ edge, const int* __restrict__ flag, int e) {
    int i = blockIdx.x * blockDim.x + threadIdx.x;
    if (i >= e) return;
    int is32 = *flag;
    int s = edge_at(ei, i, is32, 0);
    int d = edge_at(ei, i, is32, 1);
    if ((unsigned)s >= N_NODES || (unsigned)d >= N_NODES) return;
    int pos = rowptr[d] + atomicAdd(&cur[d], 1);
    edge[pos] = make_int2(s, __float_as_int(dinv[s]));
}

// ---------------- fused aggregation: one warp per dst node ----------------
__global__ void __launch_bounds__(256) k_gather(
    const int* __restrict__ rowptr, const int2* __restrict__ edge,
    const float* __restrict__ dinv, const float* __restrict__ t,
    const float* __restrict__ bias, float* __restrict__ h, int n)
{
    int d = blockIdx.x * 8 + (threadIdx.x >> 5);
    if (d >= n) return;
    int lane = threadIdx.x & 31;
    float dd = dinv[d];

    float4 acc = ((const float4*)(t + (size_t)d * HIDDEN))[lane];
    float w0 = dd * dd;
    acc.x *= w0; acc.y *= w0; acc.z *= w0; acc.w *= w0;

    int j   = rowptr[d];
    int end = rowptr[d + 1];
    for (; j + 3 < end; j += 4) {
        int2 e0 = edge[j];
        int2 e1 = edge[j + 1];
        int2 e2 = edge[j + 2];
        int2 e3 = edge[j + 3];
        float4 v0 = ((const float4*)(t + (size_t)e0.x * HIDDEN))[lane];
        float4 v1 = ((const float4*)(t + (size_t)e1.x * HIDDEN))[lane];
        float4 v2 = ((const float4*)(t + (size_t)e2.x * HIDDEN))[lane];
        float4 v3 = ((const float4*)(t + (size_t)e3.x * HIDDEN))[lane];
        float wa = __int_as_float(e0.y) * dd;
        float wb = __int_as_float(e1.y) * dd;
        float wc = __int_as_float(e2.y) * dd;
        float wd = __int_as_float(e3.y) * dd;
        acc.x = fmaf(v0.x, wa, acc.x); acc.y = fmaf(v0.y, wa, acc.y);
        acc.z = fmaf(v0.z, wa, acc.z); acc.w = fmaf(v0.w, wa, acc.w);
        acc.x = fmaf(v1.x, wb, acc.x); acc.y = fmaf(v1.y, wb, acc.y);
        acc.z = fmaf(v1.z, wb, acc.z); acc.w = fmaf(v1.w, wb, acc.w);
        acc.x = fmaf(v2.x, wc, acc.x); acc.y = fmaf(v2.y, wc, acc.y);
        acc.z = fmaf(v2.z, wc, acc.z); acc.w = fmaf(v2.w, wc, acc.w);
        acc.x = fmaf(v3.x, wd, acc.x); acc.y = fmaf(v3.y, wd, acc.y);
        acc.z = fmaf(v3.z, wd, acc.z); acc.w = fmaf(v3.w, wd, acc.w);
    }
    for (; j < end; j++) {
        int2 e0 = edge[j];
        float wa = __int_as_float(e0.y) * dd;
        float4 v0 = ((const float4*)(t + (size_t)e0.x * HIDDEN))[lane];
        acc.x = fmaf(v0.x, wa, acc.x); acc.y = fmaf(v0.y, wa, acc.y);
        acc.z = fmaf(v0.z, wa, acc.z); acc.w = fmaf(v0.w, wa, acc.w);
    }

    float4 b = *(const float4*)(bias + lane * 4);
    acc.x += b.x; acc.y += b.y; acc.z += b.z; acc.w += b.w;
    acc.x = acc.x > 0.f ? acc.x : acc.x * NEG_SLOPE;
    acc.y = acc.y > 0.f ? acc.y : acc.y * NEG_SLOPE;
    acc.z = acc.z > 0.f ? acc.z : acc.z * NEG_SLOPE;
    acc.w = acc.w > 0.f ? acc.w : acc.w * NEG_SLOPE;
    ((float4*)(h + (size_t)d * HIDDEN))[lane] = acc;
}

// ---------------- launch ----------------
extern "C" void kernel_launch(void* const* d_in, const int* in_sizes, int n_in,
                              void* d_out, int out_size)
{
    const float *x = 0, *enc_W = 0, *enc_b = 0, *conv_W = 0, *conv_b = 0, *dec_W = 0, *dec_b = 0;
    const void  *ei = 0;
    for (int i = 0; i < n_in; i++) {
        int sz = in_sizes[i];
        const void* p = d_in[i];
        switch (sz) {
            case 12800000: x      = (const float*)p; break;
            case 1600000:  ei     = p;               break;
            case 128:      enc_b  = (const float*)p; break;
            case 256:      conv_b = (const float*)p; break;
            case 8192:     dec_W  = (const float*)p; break;
            case 64:       dec_b  = (const float*)p; break;
            case 32768: {
                int nxt = (i + 1 < n_in) ? in_sizes[i + 1] : -1;
                if (nxt == 128)      enc_W  = (const float*)p;
                else if (nxt == 256) conv_W = (const float*)p;
                else if (!enc_W)     enc_W  = (const float*)p;
                else                 conv_W = (const float*)p;
                break;
            }
            default: break;
        }
    }
    float* out = (float*)d_out;

    float *dinv, *h, *tbuf;
    int *cnt, *cur, *rowptr, *bsum, *flag;
    int2 *edge;
    cudaGetSymbolAddress((void**)&dinv,   g_dinv);
    cudaGetSymbolAddress((void**)&h,      g_h);
    cudaGetSymbolAddress((void**)&tbuf,   g_t);
    cudaGetSymbolAddress((void**)&cnt,    g_cnt);
    cudaGetSymbolAddress((void**)&cur,    g_cursor);
    cudaGetSymbolAddress((void**)&rowptr, g_rowptr);
    cudaGetSymbolAddress((void**)&bsum,   g_bsum);
    cudaGetSymbolAddress((void**)&edge,   g_edge);
    cudaGetSymbolAddress((void**)&flag,   g_is32);

    const int T = 256;
    int nb_nodes = (N_NODES + T - 1) / T;
    int nb_edges = (N_EDGES + T - 1) / T;
    int nb_gemm  = (N_NODES + 127) / 128;   // 391

    // encoder at launch slot 4 (independent of CSR chain) for ncu visibility
    k_detect<<<1, 32>>>(ei, flag);                                       // 1
    k_hist_init<<<nb_nodes, T>>>(cnt, cur, N_NODES);                     // 2
    k_hist<<<nb_edges, T>>>(ei, cnt, flag, N_EDGES);                     // 3
    mma_gemm<HIDDEN><<<nb_gemm, T>>>(x, enc_W, enc_b, h,
                                     N_NODES, IN_DIM, 1);                // 4: encoder
    k_dinv<<<nb_nodes, T>>>(cnt, dinv, N_NODES);                         // 5
    k_scan1<<<NSCAN_BLOCKS, SCAN_B>>>(cnt, rowptr, bsum, N_NODES);       // 6
    k_scan2<<<1, SCAN_B>>>(bsum, NSCAN_BLOCKS);                          // 7
    k_scan3<<<NSCAN_BLOCKS, SCAN_B>>>(rowptr, bsum, N_NODES);            // 8
    k_fill<<<nb_edges, T>>>(ei, rowptr, cur, dinv, edge, flag, N_EDGES); // 9

    // 2 GCN conv layers: t = h @ W, then fused gather(+bias+lrelu) -> h
    for (int l = 0; l < 2; l++) {
        const float* W = conv_W + (size_t)l * HIDDEN * HIDDEN;
        const float* b = conv_b + (size_t)l * HIDDEN;
        mma_gemm<HIDDEN><<<nb_gemm, T>>>(h, W, nullptr, tbuf,
                                         N_NODES, HIDDEN, 0);
        k_gather<<<(N_NODES + 7) / 8, 256>>>(rowptr, edge, dinv, tbuf, b, h, N_NODES);
    }

    // decoder: out = h @ dec_W + dec_b
    mma_gemm<OUT_DIM><<<nb_gemm, T>>>(h, dec_W, dec_b, out,
                                      N_NODES, HIDDEN, 0);
}